// round 4
// baseline (speedup 1.0000x reference)
#include <cuda_runtime.h>
#include <cuda_bf16.h>

#define N_NODES 100000
#define N_EDGES 1600000
#define NRELS 8
#define HID 128
#define N_TYPES 250
#define NG 64
#define NCLS 49
#define MAXDEG 64

// ---- scratch (device globals; no allocation allowed) ----
__device__ __align__(16) float g_projr[N_TYPES * HID];                 // fp32 root proj, 128 KB
__device__ __align__(16) __nv_bfloat16 g_projh[N_TYPES * NRELS * HID]; // bf16 rel proj, 512 KB
__device__ int g_cur[N_NODES];                                         // bucket fill
__device__ unsigned short g_csr[(size_t)N_NODES * MAXDEG];             // 12.8 MB keys (t*8+r)
__device__ int g_list[N_NODES];                                        // packed n|g<<17|t<<23
__device__ int g_ncount;
__device__ float g_seg[NG * HID];
__device__ float g_segcnt[NG];

__global__ void k_zero() {
    int i = blockIdx.x * blockDim.x + threadIdx.x;
    if (i < N_NODES) g_cur[i] = 0;
    if (i < NG * HID) g_seg[i] = 0.f;
    if (i < NG) g_segcnt[i] = 0.f;
    if (i == 0) g_ncount = 0;
}

// proj = emb @ [w_rel_0..7 | w_root]; rel part stored bf16, root part fp32.
__global__ void k_proj(const float* __restrict__ emb,
                       const float* __restrict__ w_rel,
                       const float* __restrict__ w_root) {
    __shared__ float semb[10][128];
    int bx = blockIdx.x;           // 0..7 = rel r, 8 = root
    int y0 = blockIdx.y * 10;
    int tid = threadIdx.x;
    for (int idx = tid; idx < 10 * 128; idx += 128) {
        int row = idx >> 7, d = idx & 127;
        semb[row][d] = emb[(y0 + row) * 128 + d];
    }
    __syncthreads();
    float acc[10];
#pragma unroll
    for (int t = 0; t < 10; t++) acc[t] = 0.f;
    const float* wp = (bx < 8) ? (w_rel + (size_t)bx * 128 * 128 + tid)
                               : (w_root + tid);
#pragma unroll 4
    for (int d = 0; d < 128; d++) {
        float wv = wp[(size_t)d * 128];
#pragma unroll
        for (int t = 0; t < 10; t++) acc[t] += semb[t][d] * wv;
    }
    if (bx < 8) {
#pragma unroll
        for (int t = 0; t < 10; t++)
            g_projh[(y0 + t) * (NRELS * HID) + bx * HID + tid] = __float2bfloat16_rn(acc[t]);
    } else {
#pragma unroll
        for (int t = 0; t < 10; t++)
            g_projr[(y0 + t) * HID + tid] = acc[t];
    }
}

// Compact unmasked nodes; pack node id, graph id, and node's type into one int.
__global__ void k_compact(const int* __restrict__ nt,
                          const int* __restrict__ batch,
                          const int* __restrict__ x) {
    int n = blockIdx.x * blockDim.x + threadIdx.x;
    if (n >= N_NODES) return;
    if (nt[n] != 0) return;
    int g = batch[n];
    int t = x[n];
    int pos = atomicAdd(&g_ncount, 1);
    g_list[pos] = n | (g << 17) | (t << 23);
    atomicAdd(&g_segcnt[g], 1.0f);
}

// Bucket-CSR build: 4 edges/thread, skip edges into masked destinations.
__global__ void k_build(const int* __restrict__ ei,
                        const int* __restrict__ et,
                        const int* __restrict__ x,
                        const int* __restrict__ nt) {
    int e4 = blockIdx.x * blockDim.x + threadIdx.x;
    if (e4 >= N_EDGES / 4) return;
    int4 sv = ((const int4*)ei)[e4];
    int4 dv = ((const int4*)(ei + N_EDGES))[e4];
    int4 rv = ((const int4*)et)[e4];
    int ss[4] = {sv.x, sv.y, sv.z, sv.w};
    int dd[4] = {dv.x, dv.y, dv.z, dv.w};
    int rr[4] = {rv.x, rv.y, rv.z, rv.w};
#pragma unroll
    for (int j = 0; j < 4; j++) {
        int dst = dd[j];
        if (nt[dst] != 0) continue;
        int t = x[ss[j]];
        int slot = atomicAdd(&g_cur[dst], 1);
        if (slot < MAXDEG)
            g_csr[(size_t)dst * MAXDEG + slot] = (unsigned short)(t * NRELS + rr[j]);
    }
}

// One warp per unmasked node. Rel counts via ballots (rel is 3 bits), weights in
// registers, padded unroll-x4 message loop over bf16 table, ReLU, red.v4 to g_seg.
__global__ void k_gather(const float* __restrict__ bias) {
    int gt = blockIdx.x * blockDim.x + threadIdx.x;
    int idx = gt >> 5;
    int lane = gt & 31;
    if (idx >= g_ncount) return;
    int packed = g_list[idx];
    int n = packed & 0x1ffff;
    int g = (packed >> 17) & 63;
    int t0 = packed >> 23;

    float4 acc = ((const float4*)g_projr)[t0 * 32 + lane];
    float4 b = ((const float4*)bias)[lane];
    acc.x += b.x; acc.y += b.y; acc.z += b.z; acc.w += b.w;

    int deg = min(g_cur[n], MAXDEG);
    const unsigned short* row = g_csr + (size_t)n * MAXDEG;
    int ka = row[lane];
    int kb = row[lane + 32];
    int ra = ka & 7, rb = kb & 7;

    unsigned mA = (deg >= 32) ? 0xffffffffu : ((1u << deg) - 1u);
    int d2 = deg - 32;
    unsigned mB = (d2 <= 0) ? 0u : ((d2 >= 32) ? 0xffffffffu : ((1u << d2) - 1u));
    unsigned full = 0xffffffffu;
    unsigned a0 = __ballot_sync(full, ra & 1), a1 = __ballot_sync(full, ra & 2), a2 = __ballot_sync(full, ra & 4);
    unsigned b0 = __ballot_sync(full, rb & 1), b1 = __ballot_sync(full, rb & 2), b2 = __ballot_sync(full, rb & 4);
    // count of edges whose rel == ra (this lane's A-key rel)
    unsigned sa = ((ra & 1) ? a0 : ~a0) & ((ra & 2) ? a1 : ~a1) & ((ra & 4) ? a2 : ~a2);
    unsigned sb = ((ra & 1) ? b0 : ~b0) & ((ra & 2) ? b1 : ~b1) & ((ra & 4) ? b2 : ~b2);
    int ca = __popc(sa & mA) + __popc(sb & mB);
    float wa = 1.0f / fmaxf((float)ca, 1.0f);
    // count for rb (this lane's B-key rel)
    unsigned ua = ((rb & 1) ? a0 : ~a0) & ((rb & 2) ? a1 : ~a1) & ((rb & 4) ? a2 : ~a2);
    unsigned ub = ((rb & 1) ? b0 : ~b0) & ((rb & 2) ? b1 : ~b1) & ((rb & 4) ? b2 : ~b2);
    int cb = __popc(ua & mA) + __popc(ub & mB);
    float wb = 1.0f / fmaxf((float)cb, 1.0f);

    int degR = (deg + 3) & ~3;
    for (int i = 0; i < degR; i += 4) {
#pragma unroll
        for (int j = 0; j < 4; j++) {
            int i2 = i + j;
            bool hi = (i2 >= 32);
            int key = __shfl_sync(full, hi ? kb : ka, i2 & 31);
            float w = __shfl_sync(full, hi ? wb : wa, i2 & 31);
            if (i2 >= deg) w = 0.f;
            int r = key & 7;
            int t = key >> 3;
            const uint2* p = (const uint2*)(g_projh + (size_t)t * (NRELS * HID) + r * HID) + lane;
            uint2 v = *p;
            float e0 = __uint_as_float(v.x << 16);
            float e1 = __uint_as_float(v.x & 0xffff0000u);
            float e2 = __uint_as_float(v.y << 16);
            float e3 = __uint_as_float(v.y & 0xffff0000u);
            acc.x += e0 * w; acc.y += e1 * w; acc.z += e2 * w; acc.w += e3 * w;
        }
    }

    acc.x = fmaxf(acc.x, 0.f); acc.y = fmaxf(acc.y, 0.f);
    acc.z = fmaxf(acc.z, 0.f); acc.w = fmaxf(acc.w, 0.f);

    float* dstp = &g_seg[g * HID + lane * 4];
    asm volatile("red.global.add.v4.f32 [%0], {%1,%2,%3,%4};"
                 :: "l"(dstp), "f"(acc.x), "f"(acc.y), "f"(acc.z), "f"(acc.w)
                 : "memory");
}

// out[g][o] = (seg[g]/max(cnt,1)) . lin_w[o] + lin_b[o]
__global__ void k_out(const float* __restrict__ lw,
                      const float* __restrict__ lb,
                      float* __restrict__ out) {
    __shared__ float s[128];
    int g = blockIdx.x, tid = threadIdx.x;
    float c = g_segcnt[g];
    float inv = 1.0f / fmaxf(c, 1.0f);
    s[tid] = g_seg[g * HID + tid] * inv;
    __syncthreads();
    if (tid < NCLS) {
        float acc = lb[tid];
#pragma unroll 4
        for (int d = 0; d < 128; d++) acc += s[d] * lw[tid * 128 + d];
        out[g * NCLS + tid] = acc;
    }
}

extern "C" void kernel_launch(void* const* d_in, const int* in_sizes, int n_in,
                              void* d_out, int out_size) {
    int o = (n_in >= 12) ? 1 : 0;
    const int* x     = (const int*)d_in[0];
    const int* ei    = (const int*)d_in[1];
    const int* et    = (const int*)d_in[2];
    const int* batch = (const int*)d_in[3];
    const int* nt    = (const int*)d_in[4];
    const float* emb    = (const float*)d_in[5 + o];
    const float* w_root = (const float*)d_in[6 + o];
    const float* w_rel  = (const float*)d_in[7 + o];
    const float* bias   = (const float*)d_in[8 + o];
    const float* lw     = (const float*)d_in[9 + o];
    const float* lb     = (const float*)d_in[10 + o];
    float* out = (float*)d_out;

    k_zero<<<(N_NODES + 255) / 256, 256>>>();
    k_proj<<<dim3(9, 25), 128>>>(emb, w_rel, w_root);
    k_compact<<<(N_NODES + 255) / 256, 256>>>(nt, batch, x);
    k_build<<<(N_EDGES / 4 + 255) / 256, 256>>>(ei, et, x, nt);
    k_gather<<<(N_NODES * 32 + 255) / 256, 256>>>(bias);
    k_out<<<NG, 128>>>(lw, lb, out);
    (void)in_sizes; (void)out_size;
}

// round 5
// speedup vs baseline: 1.6406x; 1.6406x over previous
#include <cuda_runtime.h>
#include <cuda_bf16.h>

#define N_NODES 100000
#define N_EDGES 1600000
#define NRELS 8
#define HID 128
#define N_TYPES 250
#define NG 64
#define NCLS 49
#define MAXDEG 64

// ---- scratch (device globals; no allocation allowed) ----
__device__ __align__(16) float g_projr[N_TYPES * HID];                 // fp32 root proj, 128 KB
__device__ __align__(16) __nv_bfloat16 g_projh[N_TYPES * NRELS * HID]; // bf16 rel proj, 512 KB
__device__ int g_cur[N_NODES];                                         // bucket fill
__device__ unsigned short g_csr[(size_t)N_NODES * MAXDEG];             // 12.8 MB keys (t*8+r)
__device__ unsigned char g_type8[N_NODES];                             // 100 KB, L1-resident
__device__ unsigned char g_msk[N_NODES];                               // 100 KB, L1-resident
__device__ int g_list[N_NODES];                                        // packed n|g<<17|t<<23
__device__ int g_ncount;
__device__ float g_seg[NG * HID];
__device__ float g_segcnt[NG];

__global__ void k_zero() {
    int i = blockIdx.x * blockDim.x + threadIdx.x;
    if (i < N_NODES) g_cur[i] = 0;
    if (i < NG * HID) g_seg[i] = 0.f;
    if (i < NG) g_segcnt[i] = 0.f;
    if (i == 0) g_ncount = 0;
}

// proj = emb @ [w_rel_0..7 | w_root]; rel part stored bf16, root part fp32.
__global__ void k_proj(const float* __restrict__ emb,
                       const float* __restrict__ w_rel,
                       const float* __restrict__ w_root) {
    __shared__ float semb[10][128];
    int bx = blockIdx.x;           // 0..7 = rel r, 8 = root
    int y0 = blockIdx.y * 10;
    int tid = threadIdx.x;
    for (int idx = tid; idx < 10 * 128; idx += 128) {
        int row = idx >> 7, d = idx & 127;
        semb[row][d] = emb[(y0 + row) * 128 + d];
    }
    __syncthreads();
    float acc[10];
#pragma unroll
    for (int t = 0; t < 10; t++) acc[t] = 0.f;
    const float* wp = (bx < 8) ? (w_rel + (size_t)bx * 128 * 128 + tid)
                               : (w_root + tid);
#pragma unroll 4
    for (int d = 0; d < 128; d++) {
        float wv = wp[(size_t)d * 128];
#pragma unroll
        for (int t = 0; t < 10; t++) acc[t] += semb[t][d] * wv;
    }
    if (bx < 8) {
#pragma unroll
        for (int t = 0; t < 10; t++)
            g_projh[(y0 + t) * (NRELS * HID) + bx * HID + tid] = __float2bfloat16_rn(acc[t]);
    } else {
#pragma unroll
        for (int t = 0; t < 10; t++)
            g_projr[(y0 + t) * HID + tid] = acc[t];
    }
}

// One coalesced pass over nodes: byte tables for k_build, warp-aggregated
// compaction of unmasked nodes, match-aggregated per-graph counts.
__global__ void k_prep(const int* __restrict__ x,
                       const int* __restrict__ nt,
                       const int* __restrict__ batch) {
    int n = blockIdx.x * blockDim.x + threadIdx.x;
    int lane = threadIdx.x & 31;
    bool valid = (n < N_NODES);
    int t = 0, m = 1, g = 0;
    if (valid) {
        t = x[n]; m = nt[n]; g = batch[n];
        g_type8[n] = (unsigned char)t;
        g_msk[n] = (m == 0) ? 1 : 0;
    }
    bool keep = valid && (m == 0);
    unsigned full = 0xffffffffu;
    unsigned ball = __ballot_sync(full, keep);
    int cnt = __popc(ball);
    int base = 0;
    if (lane == 0 && cnt) base = atomicAdd(&g_ncount, cnt);
    base = __shfl_sync(full, base, 0);
    if (keep) {
        int pos = base + __popc(ball & ((1u << lane) - 1u));
        g_list[pos] = n | (g << 17) | (t << 23);
    }
    unsigned grp = __match_any_sync(full, keep ? g : -1);
    if (keep && lane == (__ffs(grp) - 1))
        atomicAdd(&g_segcnt[g], (float)__popc(grp));
}

// Bucket-CSR build: 8 edges/thread, L1-resident byte tables for mask/type.
__global__ void k_build(const int* __restrict__ ei,
                        const int* __restrict__ et) {
    int e8 = blockIdx.x * blockDim.x + threadIdx.x;
    if (e8 >= N_EDGES / 8) return;
    const int4* s4 = (const int4*)ei;
    const int4* d4 = (const int4*)(ei + N_EDGES);
    const int4* r4 = (const int4*)et;
    int4 sa = s4[e8 * 2], sb = s4[e8 * 2 + 1];
    int4 da = d4[e8 * 2], db = d4[e8 * 2 + 1];
    int4 ra = r4[e8 * 2], rb = r4[e8 * 2 + 1];
    int ss[8] = {sa.x, sa.y, sa.z, sa.w, sb.x, sb.y, sb.z, sb.w};
    int dd[8] = {da.x, da.y, da.z, da.w, db.x, db.y, db.z, db.w};
    int rr[8] = {ra.x, ra.y, ra.z, ra.w, rb.x, rb.y, rb.z, rb.w};
    unsigned char mk[8];
#pragma unroll
    for (int j = 0; j < 8; j++) mk[j] = g_msk[dd[j]];
#pragma unroll
    for (int j = 0; j < 8; j++) {
        if (!mk[j]) continue;
        int t = g_type8[ss[j]];
        int slot = atomicAdd(&g_cur[dd[j]], 1);
        if (slot < MAXDEG)
            g_csr[(size_t)dd[j] * MAXDEG + slot] = (unsigned short)(t * NRELS + rr[j]);
    }
}

// One warp per unmasked node. Rel counts via ballots, (key,weight) staged in
// smem once, then unroll-x8 broadcast-LDS + LDG.64 message loop, ReLU, red.v4.
__global__ void k_gather(const float* __restrict__ bias) {
    __shared__ float2 sbuf[8][MAXDEG];
    int gt = blockIdx.x * blockDim.x + threadIdx.x;
    int idx = gt >> 5;
    int lane = gt & 31;
    int wslot = (threadIdx.x >> 5);
    if (idx >= g_ncount) return;
    int packed = g_list[idx];
    int n = packed & 0x1ffff;
    int g = (packed >> 17) & 63;
    int t0 = packed >> 23;

    float4 acc = ((const float4*)g_projr)[t0 * 32 + lane];
    float4 b = ((const float4*)bias)[lane];
    acc.x += b.x; acc.y += b.y; acc.z += b.z; acc.w += b.w;

    int deg = min(g_cur[n], MAXDEG);
    const unsigned short* row = g_csr + (size_t)n * MAXDEG;
    int ka = row[lane];
    int kb = row[lane + 32];
    int ra = ka & 7, rb = kb & 7;

    unsigned mA = (deg >= 32) ? 0xffffffffu : ((1u << deg) - 1u);
    int d2 = deg - 32;
    unsigned mB = (d2 <= 0) ? 0u : ((d2 >= 32) ? 0xffffffffu : ((1u << d2) - 1u));
    unsigned full = 0xffffffffu;
    unsigned a0 = __ballot_sync(full, ra & 1), a1 = __ballot_sync(full, ra & 2), a2 = __ballot_sync(full, ra & 4);
    unsigned b0 = __ballot_sync(full, rb & 1), b1 = __ballot_sync(full, rb & 2), b2 = __ballot_sync(full, rb & 4);
    unsigned sa = ((ra & 1) ? a0 : ~a0) & ((ra & 2) ? a1 : ~a1) & ((ra & 4) ? a2 : ~a2);
    unsigned sb = ((ra & 1) ? b0 : ~b0) & ((ra & 2) ? b1 : ~b1) & ((ra & 4) ? b2 : ~b2);
    int ca = __popc(sa & mA) + __popc(sb & mB);
    float wa = 1.0f / fmaxf((float)ca, 1.0f);
    unsigned ua = ((rb & 1) ? a0 : ~a0) & ((rb & 2) ? a1 : ~a1) & ((rb & 4) ? a2 : ~a2);
    unsigned ub = ((rb & 1) ? b0 : ~b0) & ((rb & 2) ? b1 : ~b1) & ((rb & 4) ? b2 : ~b2);
    int cb = __popc(ua & mA) + __popc(ub & mB);
    float wb = 1.0f / fmaxf((float)cb, 1.0f);

    sbuf[wslot][lane]      = make_float2(wa, __int_as_float(ka));
    sbuf[wslot][lane + 32] = make_float2(wb, __int_as_float(kb));
    __syncwarp();

    const uint2* ph = (const uint2*)g_projh;
    int degR = (deg + 7) & ~7;
    for (int i = 0; i < degR; i += 8) {
#pragma unroll
        for (int j = 0; j < 8; j++) {
            int i2 = i + j;
            float2 kw = sbuf[wslot][i2];
            float w = (i2 < deg) ? kw.x : 0.f;
            int key = __float_as_int(kw.y);
            uint2 v = ph[(size_t)key * 32 + lane];
            float e0 = __uint_as_float(v.x << 16);
            float e1 = __uint_as_float(v.x & 0xffff0000u);
            float e2 = __uint_as_float(v.y << 16);
            float e3 = __uint_as_float(v.y & 0xffff0000u);
            acc.x += e0 * w; acc.y += e1 * w; acc.z += e2 * w; acc.w += e3 * w;
        }
    }

    acc.x = fmaxf(acc.x, 0.f); acc.y = fmaxf(acc.y, 0.f);
    acc.z = fmaxf(acc.z, 0.f); acc.w = fmaxf(acc.w, 0.f);

    float* dstp = &g_seg[g * HID + lane * 4];
    asm volatile("red.global.add.v4.f32 [%0], {%1,%2,%3,%4};"
                 :: "l"(dstp), "f"(acc.x), "f"(acc.y), "f"(acc.z), "f"(acc.w)
                 : "memory");
}

// out[g][o] = (seg[g]/max(cnt,1)) . lin_w[o] + lin_b[o]
__global__ void k_out(const float* __restrict__ lw,
                      const float* __restrict__ lb,
                      float* __restrict__ out) {
    __shared__ float s[128];
    int g = blockIdx.x, tid = threadIdx.x;
    float c = g_segcnt[g];
    float inv = 1.0f / fmaxf(c, 1.0f);
    s[tid] = g_seg[g * HID + tid] * inv;
    __syncthreads();
    if (tid < NCLS) {
        float acc = lb[tid];
#pragma unroll 4
        for (int d = 0; d < 128; d++) acc += s[d] * lw[tid * 128 + d];
        out[g * NCLS + tid] = acc;
    }
}

extern "C" void kernel_launch(void* const* d_in, const int* in_sizes, int n_in,
                              void* d_out, int out_size) {
    int o = (n_in >= 12) ? 1 : 0;
    const int* x     = (const int*)d_in[0];
    const int* ei    = (const int*)d_in[1];
    const int* et    = (const int*)d_in[2];
    const int* batch = (const int*)d_in[3];
    const int* nt    = (const int*)d_in[4];
    const float* emb    = (const float*)d_in[5 + o];
    const float* w_root = (const float*)d_in[6 + o];
    const float* w_rel  = (const float*)d_in[7 + o];
    const float* bias   = (const float*)d_in[8 + o];
    const float* lw     = (const float*)d_in[9 + o];
    const float* lb     = (const float*)d_in[10 + o];
    float* out = (float*)d_out;

    k_zero<<<(N_NODES + 255) / 256, 256>>>();
    k_proj<<<dim3(9, 25), 128>>>(emb, w_rel, w_root);
    k_prep<<<(N_NODES + 255) / 256, 256>>>(x, nt, batch);
    k_build<<<(N_EDGES / 8 + 255) / 256, 256>>>(ei, et);
    k_gather<<<(N_NODES * 32 + 255) / 256, 256>>>(bias);
    k_out<<<NG, 128>>>(lw, lb, out);
    (void)in_sizes; (void)out_size;
}